// round 1
// baseline (speedup 1.0000x reference)
#include <cuda_runtime.h>
#include <math.h>

// ---------------- problem constants (fixed by reference) ----------------
#define NN    20000
#define EE    400000
#define ET    (EE + NN)      // edges + self loops
#define GG    200
#define HH    4
#define C1    64
#define C2    32
#define INF_  8

// ---------------- persistent scratch (__device__ globals; no alloc) -----
__device__ float g_xl[NN * 256];       // per-layer lin_l features (layer1: 256, layer2: 128)
__device__ float g_xr[NN * 256];       // per-layer lin_r features
__device__ float g_h [NN * 64];        // node activations between layers / final
__device__ int   g_deg[NN];
__device__ int   g_tmp[NN];
__device__ int   g_rowptr[NN + 1];
__device__ int   g_csr[ET];            // src index per (dst-sorted) edge
__device__ int   g_cnt[GG];

__device__ __forceinline__ float lrelu(float v) { return v > 0.f ? v : 0.2f * v; }

// ---------------- init ----------------
__global__ void zero_kernel(float* __restrict__ dout) {
    int i = blockIdx.x * blockDim.x + threadIdx.x;
    if (i < NN) { g_deg[i] = 0; g_tmp[i] = 0; }
    if (i < GG) g_cnt[i] = 0;
    if (i < GG * C2) dout[i] = 0.f;
}

// ---------------- CSR build ----------------
__global__ void count_kernel(const int* __restrict__ ei, const int* __restrict__ batch) {
    int i = blockIdx.x * blockDim.x + threadIdx.x;
    if (i < ET) {
        int dst = (i < EE) ? ei[EE + i] : (i - EE);
        atomicAdd(&g_deg[dst], 1);
    }
    if (i < NN) atomicAdd(&g_cnt[batch[i]], 1);
}

__global__ void scan_kernel() {
    __shared__ int sbuf[1024];
    int t = threadIdx.x;
    const int CH = (NN + 1023) / 1024;
    int lo = t * CH;
    int hi = lo + CH; if (hi > NN) hi = NN; if (lo > NN) lo = NN;
    int s = 0;
    for (int i = lo; i < hi; i++) s += g_deg[i];
    sbuf[t] = s;
    __syncthreads();
    for (int off = 1; off < 1024; off <<= 1) {
        int v = (t >= off) ? sbuf[t - off] : 0;
        __syncthreads();
        sbuf[t] += v;
        __syncthreads();
    }
    int run = sbuf[t] - s;  // exclusive base
    for (int i = lo; i < hi; i++) { g_rowptr[i] = run; run += g_deg[i]; }
    if (t == 1023) g_rowptr[NN] = sbuf[1023];
}

__global__ void fill_kernel(const int* __restrict__ ei) {
    int i = blockIdx.x * blockDim.x + threadIdx.x;
    if (i >= ET) return;
    int src, dst;
    if (i < EE) { src = ei[i]; dst = ei[EE + i]; }
    else        { src = dst = i - EE; }
    int pos = atomicAdd(&g_tmp[dst], 1);
    g_csr[g_rowptr[dst] + pos] = src;
}

// ---------------- register-tiled linear:  [N,K] @ [K,DT/2]x2 + bias -----
// Block handles 32 nodes x all DT cols. Each thread: 8 rows x 4 cols (float4).
template <int K, int DT>
__global__ void lin_kernel(const float* __restrict__ x,
                           const float* __restrict__ Wl, const float* __restrict__ bl,
                           const float* __restrict__ Wr, const float* __restrict__ br,
                           float* __restrict__ xl, float* __restrict__ xr) {
    constexpr int DH = DT / 2;
    constexpr int MB = 32;
    constexpr int CT = DT / 4;          // column-group threads
    __shared__ float xs[MB * K];
    int n0 = blockIdx.x * MB;
    int tid = threadIdx.x;
    for (int idx = tid; idx < MB * K; idx += blockDim.x)
        xs[idx] = x[n0 * K + idx];
    __syncthreads();

    int co  = tid % CT;
    int ro  = tid / CT;                 // 0..3
    int col = co * 4;
    int r0  = ro * 8;
    const float* W    = (col < DH) ? (Wl + col)      : (Wr + col - DH);
    const float* bptr = (col < DH) ? (bl + col)      : (br + col - DH);
    float4 bv = *reinterpret_cast<const float4*>(bptr);
    float4 acc[8];
#pragma unroll
    for (int i = 0; i < 8; i++) acc[i] = bv;

#pragma unroll 8
    for (int k = 0; k < K; k++) {
        float4 w = *reinterpret_cast<const float4*>(W + k * DH);
#pragma unroll
        for (int i = 0; i < 8; i++) {
            float xv = xs[(r0 + i) * K + k];
            acc[i].x += xv * w.x;
            acc[i].y += xv * w.y;
            acc[i].z += xv * w.z;
            acc[i].w += xv * w.w;
        }
    }
    float* outp = (col < DH) ? xl : xr;
    int ocol = (col < DH) ? col : col - DH;
#pragma unroll
    for (int i = 0; i < 8; i++)
        *reinterpret_cast<float4*>(outp + (size_t)(n0 + r0 + i) * DH + ocol) = acc[i];
}

// ---------------- GATv2 aggregation: one warp per dst node --------------
// Lane layout: float4 slot f covers idx 4*(lane+32f)..+3 of the [H*C] row.
// Head h = 4j/C is constant per float4; lanes with equal h form aligned
// groups of GS = C/4 lanes -> score reduce via SHFL.BFLY inside group.
template <int C>
__global__ void gat_kernel(const float* __restrict__ xl, const float* __restrict__ xr,
                           const float* __restrict__ att, const float* __restrict__ bias,
                           const float* __restrict__ lng, const float* __restrict__ lnb,
                           float* __restrict__ out) {
    constexpr int D  = 4 * C;       // H*C
    constexpr int F  = D / 128;     // float4 slots per lane (2 for C=64, 1 for C=32)
    constexpr int GS = C / 4;       // lanes per head group
    int gw = (blockIdx.x * blockDim.x + threadIdx.x) >> 5;
    if (gw >= NN) return;
    int lane = threadIdx.x & 31;
    const float4* xl4 = reinterpret_cast<const float4*>(xl);
    const float4* xr4 = reinterpret_cast<const float4*>(xr);

    float4 a4[F], q4[F], acc[F];
    float m[F], s[F];
#pragma unroll
    for (int f = 0; f < F; f++) {
        int j = lane + 32 * f;
        int h = (4 * j) / C;
        int c0 = 4 * j - h * C;
        a4[f] = *reinterpret_cast<const float4*>(att + h * C + c0);
        q4[f] = xr4[(size_t)gw * (D / 4) + j];
        acc[f] = make_float4(0.f, 0.f, 0.f, 0.f);
        m[f] = -1e30f;
        s[f] = 0.f;
    }

    int kb = g_rowptr[gw], ke = g_rowptr[gw + 1];
    int src = g_csr[kb];
    for (int k = kb; k < ke; k++) {
        float4 xv[F];
#pragma unroll
        for (int f = 0; f < F; f++)
            xv[f] = xl4[(size_t)src * (D / 4) + lane + 32 * f];
        if (k + 1 < ke) src = g_csr[k + 1];   // prefetch next src index
#pragma unroll
        for (int f = 0; f < F; f++) {
            float ex = xv[f].x + q4[f].x;
            float ey = xv[f].y + q4[f].y;
            float ez = xv[f].z + q4[f].z;
            float ew = xv[f].w + q4[f].w;
            float p = a4[f].x * lrelu(ex) + a4[f].y * lrelu(ey)
                    + a4[f].z * lrelu(ez) + a4[f].w * lrelu(ew);
#pragma unroll
            for (int off = GS / 2; off >= 1; off >>= 1)
                p += __shfl_xor_sync(0xffffffffu, p, off);
            // p is now score[h(f)] for this lane's head; online softmax update
            float nm = fmaxf(m[f], p);
            float sc = __expf(m[f] - nm);
            float al = __expf(p - nm);
            s[f] = s[f] * sc + al;
            acc[f].x = acc[f].x * sc + al * xv[f].x;
            acc[f].y = acc[f].y * sc + al * xv[f].y;
            acc[f].z = acc[f].z * sc + al * xv[f].z;
            acc[f].w = acc[f].w * sc + al * xv[f].w;
            m[f] = nm;
        }
    }

    // normalize + head mean (reduce across head-groups)
    float4 u = make_float4(0.f, 0.f, 0.f, 0.f);
#pragma unroll
    for (int f = 0; f < F; f++) {
        float inv = 1.f / s[f];
        u.x += acc[f].x * inv;
        u.y += acc[f].y * inv;
        u.z += acc[f].z * inv;
        u.w += acc[f].w * inv;
    }
#pragma unroll
    for (int off = GS; off < 32; off <<= 1) {
        u.x += __shfl_xor_sync(0xffffffffu, u.x, off);
        u.y += __shfl_xor_sync(0xffffffffu, u.y, off);
        u.z += __shfl_xor_sync(0xffffffffu, u.z, off);
        u.w += __shfl_xor_sync(0xffffffffu, u.w, off);
    }
    int cl = lane & (GS - 1);
    float4 bv = *reinterpret_cast<const float4*>(bias + 4 * cl);
    u.x = u.x * 0.25f + bv.x;
    u.y = u.y * 0.25f + bv.y;
    u.z = u.z * 0.25f + bv.z;
    u.w = u.w * 0.25f + bv.w;

    // LayerNorm over C (values replicated 32/GS times; 32/GS * C == 128)
    float tot = u.x + u.y + u.z + u.w;
#pragma unroll
    for (int off = 16; off >= 1; off >>= 1)
        tot += __shfl_xor_sync(0xffffffffu, tot, off);
    float mean = tot * (1.f / 128.f);
    float dx = u.x - mean, dy = u.y - mean, dz = u.z - mean, dw = u.w - mean;
    float v = dx * dx + dy * dy + dz * dz + dw * dw;
#pragma unroll
    for (int off = 16; off >= 1; off >>= 1)
        v += __shfl_xor_sync(0xffffffffu, v, off);
    float rstd = rsqrtf(v * (1.f / 128.f) + 1e-5f);
    float4 gv = *reinterpret_cast<const float4*>(lng + 4 * cl);
    float4 b2 = *reinterpret_cast<const float4*>(lnb + 4 * cl);
    float4 y;
    y.x = fmaxf(dx * rstd * gv.x + b2.x, 0.f);
    y.y = fmaxf(dy * rstd * gv.y + b2.y, 0.f);
    y.z = fmaxf(dz * rstd * gv.z + b2.z, 0.f);
    y.w = fmaxf(dw * rstd * gv.w + b2.w, 0.f);
    if (lane < GS)
        *reinterpret_cast<float4*>(out + (size_t)gw * C + 4 * cl) = y;
}

// ---------------- global mean pool ----------------
__global__ void pool_kernel(const float* __restrict__ h, const int* __restrict__ batch,
                            float* __restrict__ out) {
    int i = blockIdx.x * blockDim.x + threadIdx.x;
    if (i >= NN * C2) return;
    int node = i / C2, c = i % C2;
    atomicAdd(&out[batch[node] * C2 + c], h[i]);
}

__global__ void div_kernel(float* __restrict__ out) {
    int i = blockIdx.x * blockDim.x + threadIdx.x;
    if (i >= GG * C2) return;
    out[i] /= fmaxf((float)g_cnt[i / C2], 1.f);
}

// ---------------- launch ----------------
extern "C" void kernel_launch(void* const* d_in, const int* in_sizes, int n_in,
                              void* d_out, int out_size) {
    const float* x     = (const float*)d_in[0];
    const int*   ei    = (const int*)  d_in[1];
    const int*   batch = (const int*)  d_in[2];
    const float* Wl1   = (const float*)d_in[3];
    const float* bl1   = (const float*)d_in[4];
    const float* Wr1   = (const float*)d_in[5];
    const float* br1   = (const float*)d_in[6];
    const float* att1  = (const float*)d_in[7];
    const float* b1    = (const float*)d_in[8];
    const float* ln1g  = (const float*)d_in[9];
    const float* ln1b  = (const float*)d_in[10];
    const float* Wl2   = (const float*)d_in[11];
    const float* bl2   = (const float*)d_in[12];
    const float* Wr2   = (const float*)d_in[13];
    const float* br2   = (const float*)d_in[14];
    const float* att2  = (const float*)d_in[15];
    const float* b2    = (const float*)d_in[16];
    const float* ln2g  = (const float*)d_in[17];
    const float* ln2b  = (const float*)d_in[18];
    float* out = (float*)d_out;

    float *xl, *xr, *h;
    cudaGetSymbolAddress((void**)&xl, g_xl);
    cudaGetSymbolAddress((void**)&xr, g_xr);
    cudaGetSymbolAddress((void**)&h,  g_h);

    zero_kernel <<<(NN + 255) / 256, 256>>>(out);
    count_kernel<<<(ET + 255) / 256, 256>>>(ei, batch);
    scan_kernel <<<1, 1024>>>();
    fill_kernel <<<(ET + 255) / 256, 256>>>(ei);

    lin_kernel<INF_, 512><<<NN / 32, 512>>>(x, Wl1, bl1, Wr1, br1, xl, xr);
    gat_kernel<C1><<<NN / 8, 256>>>(xl, xr, att1, b1, ln1g, ln1b, h);
    lin_kernel<C1, 256><<<NN / 32, 256>>>(h, Wl2, bl2, Wr2, br2, xl, xr);
    gat_kernel<C2><<<NN / 8, 256>>>(xl, xr, att2, b2, ln2g, ln2b, h);

    pool_kernel<<<(NN * C2 + 255) / 256, 256>>>(h, batch, out);
    div_kernel <<<(GG * C2 + 255) / 256, 256>>>(out);
}

// round 2
// speedup vs baseline: 1.1141x; 1.1141x over previous
#include <cuda_runtime.h>
#include <cuda_fp16.h>
#include <math.h>

// ---------------- problem constants ----------------
#define NN    20000
#define EE    400000
#define ET    (EE + NN)
#define GG    200
#define C1    64
#define C2    32
#define INF_  8

// ---------------- persistent scratch ----------------
__device__ __align__(16) __half g_xl[NN * 256];   // fp16 gathered message table
__device__ __align__(16) float  g_xr[NN * 256];   // fp32 query table
__device__ __align__(16) float  g_h [NN * 64];    // inter-layer activations
__device__ __align__(16) int    g_deg[NN];
__device__ __align__(16) int    g_tmp[NN];
__device__ __align__(16) int    g_rowptr[NN + 4];
__device__ int                  g_csr[ET];

__device__ __forceinline__ float lrelu(float v) { return v > 0.f ? v : 0.2f * v; }

// ---------------- init: deg=1 (self loop), zero output ----------------
__global__ void zero_kernel(float* __restrict__ dout) {
    int i = blockIdx.x * blockDim.x + threadIdx.x;
    if (i < NN) g_deg[i] = 1;
    if (i < GG * C2) dout[i] = 0.f;
}

// ---------------- CSR: count (vectorized) ----------------
__global__ void count_kernel(const int* __restrict__ ei) {
    int i = blockIdx.x * blockDim.x + threadIdx.x;
    if (i >= EE / 4) return;
    int4 d = reinterpret_cast<const int4*>(ei + EE)[i];
    atomicAdd(&g_deg[d.x], 1);
    atomicAdd(&g_deg[d.y], 1);
    atomicAdd(&g_deg[d.z], 1);
    atomicAdd(&g_deg[d.w], 1);
}

// ---------------- CSR: scan (single block, int4 I/O) ----------------
__global__ void scan_kernel() {
    __shared__ int sbuf[1024];
    int t = threadIdx.x;
    int4 v[5];
    int s = 0;
    const int4* d4 = reinterpret_cast<const int4*>(g_deg);
    if (t < 1000) {
#pragma unroll
        for (int i = 0; i < 5; i++) {
            v[i] = d4[t * 5 + i];
            s += v[i].x + v[i].y + v[i].z + v[i].w;
        }
    }
    sbuf[t] = s;
    __syncthreads();
#pragma unroll
    for (int off = 1; off < 1024; off <<= 1) {
        int vv = (t >= off) ? sbuf[t - off] : 0;
        __syncthreads();
        sbuf[t] += vv;
        __syncthreads();
    }
    if (t < 1000) {
        int run = sbuf[t] - s;
        int4* rp4 = reinterpret_cast<int4*>(g_rowptr);
        int4* tp4 = reinterpret_cast<int4*>(g_tmp);
#pragma unroll
        for (int i = 0; i < 5; i++) {
            int4 o;
            o.x = run; run += v[i].x;
            o.y = run; run += v[i].y;
            o.z = run; run += v[i].z;
            o.w = run; run += v[i].w;
            rp4[t * 5 + i] = o;
            tp4[t * 5 + i] = o;
        }
    }
    if (t == 1023) g_rowptr[NN] = sbuf[1023];
}

// ---------------- CSR: fill (vectorized, no rowptr reload) ----------------
__global__ void fill_kernel(const int* __restrict__ ei) {
    int i = blockIdx.x * blockDim.x + threadIdx.x;
    if (i >= ET / 4) return;
    if (i < EE / 4) {
        int4 s4 = reinterpret_cast<const int4*>(ei)[i];
        int4 d4 = reinterpret_cast<const int4*>(ei + EE)[i];
        int p;
        p = atomicAdd(&g_tmp[d4.x], 1); g_csr[p] = s4.x;
        p = atomicAdd(&g_tmp[d4.y], 1); g_csr[p] = s4.y;
        p = atomicAdd(&g_tmp[d4.z], 1); g_csr[p] = s4.z;
        p = atomicAdd(&g_tmp[d4.w], 1); g_csr[p] = s4.w;
    } else {
        int n = 4 * i - EE;
#pragma unroll
        for (int j = 0; j < 4; j++) {
            int p = atomicAdd(&g_tmp[n + j], 1);
            g_csr[p] = n + j;
        }
    }
}

// ---------------- register-tiled linear; xl stored fp16, xr fp32 ------
template <int K, int DT>
__global__ void lin_kernel(const float* __restrict__ x,
                           const float* __restrict__ Wl, const float* __restrict__ bl,
                           const float* __restrict__ Wr, const float* __restrict__ br,
                           __half* __restrict__ xl, float* __restrict__ xr) {
    constexpr int DH = DT / 2;
    constexpr int MB = 32;
    constexpr int CT = DT / 4;
    __shared__ float xs[MB * K];
    int n0 = blockIdx.x * MB;
    int tid = threadIdx.x;
    for (int idx = tid; idx < MB * K; idx += blockDim.x)
        xs[idx] = x[n0 * K + idx];
    __syncthreads();

    int co  = tid % CT;
    int ro  = tid / CT;
    int col = co * 4;
    int r0  = ro * 8;
    bool left = (col < DH);
    const float* W    = left ? (Wl + col) : (Wr + col - DH);
    const float* bptr = left ? (bl + col) : (br + col - DH);
    float4 bv = *reinterpret_cast<const float4*>(bptr);
    float4 acc[8];
#pragma unroll
    for (int i = 0; i < 8; i++) acc[i] = bv;

#pragma unroll 8
    for (int k = 0; k < K; k++) {
        float4 w = *reinterpret_cast<const float4*>(W + k * DH);
#pragma unroll
        for (int i = 0; i < 8; i++) {
            float xv = xs[(r0 + i) * K + k];
            acc[i].x += xv * w.x;
            acc[i].y += xv * w.y;
            acc[i].z += xv * w.z;
            acc[i].w += xv * w.w;
        }
    }
    if (left) {
#pragma unroll
        for (int i = 0; i < 8; i++) {
            __half2* p = reinterpret_cast<__half2*>(xl + (size_t)(n0 + r0 + i) * DH + col);
            p[0] = __floats2half2_rn(acc[i].x, acc[i].y);
            p[1] = __floats2half2_rn(acc[i].z, acc[i].w);
        }
    } else {
        int oc = col - DH;
#pragma unroll
        for (int i = 0; i < 8; i++)
            *reinterpret_cast<float4*>(xr + (size_t)(n0 + r0 + i) * DH + oc) = acc[i];
    }
}

// ---------------- GATv2: one warp per dst node, fp16 gathers ----------
// Lane layout: D = 4*C values per row; lane L owns values L*VPL..L*VPL+VPL-1
// where VPL = C/8. head = L/8, group of 8 lanes per head.
template <int C, bool FINAL>
__global__ void gat_kernel(const __half* __restrict__ xl, const float* __restrict__ xr,
                           const float* __restrict__ att, const float* __restrict__ bias,
                           const float* __restrict__ lng, const float* __restrict__ lnb,
                           const int* __restrict__ batch, float* __restrict__ outp) {
    constexpr int D   = 4 * C;
    constexpr int VPL = C / 8;
    int gw = (blockIdx.x * blockDim.x + threadIdx.x) >> 5;
    if (gw >= NN) return;
    int lane = threadIdx.x & 31;
    int h  = lane >> 3;
    int cl = lane & 7;

    float a[VPL], q[VPL], acc[VPL];
    const float* attp = att + h * C + cl * VPL;
    const float* qp   = xr + (size_t)gw * D + lane * VPL;
#pragma unroll
    for (int i = 0; i < VPL; i++) { a[i] = attp[i]; q[i] = qp[i]; acc[i] = 0.f; }
    float m = -1e30f, s = 0.f;

    int kb = g_rowptr[gw], ke = g_rowptr[gw + 1];
    int src = g_csr[kb];
    for (int k = kb; k < ke; k++) {
        float xv[VPL];
        if (C == 64) {
            uint4 u = *reinterpret_cast<const uint4*>(xl + (size_t)src * D + lane * VPL);
            float2 f;
            f = __half22float2(*reinterpret_cast<__half2*>(&u.x)); xv[0] = f.x; xv[1] = f.y;
            f = __half22float2(*reinterpret_cast<__half2*>(&u.y)); xv[2] = f.x; xv[3] = f.y;
            f = __half22float2(*reinterpret_cast<__half2*>(&u.z)); xv[4] = f.x; xv[5] = f.y;
            f = __half22float2(*reinterpret_cast<__half2*>(&u.w)); xv[6] = f.x; xv[7] = f.y;
        } else {
            uint2 u = *reinterpret_cast<const uint2*>(xl + (size_t)src * D + lane * VPL);
            float2 f;
            f = __half22float2(*reinterpret_cast<__half2*>(&u.x)); xv[0] = f.x; xv[1] = f.y;
            f = __half22float2(*reinterpret_cast<__half2*>(&u.y)); xv[2] = f.x; xv[3] = f.y;
        }
        if (k + 1 < ke) src = g_csr[k + 1];       // prefetch next src index
        float p = 0.f;
#pragma unroll
        for (int i = 0; i < VPL; i++) p += a[i] * lrelu(xv[i] + q[i]);
        p += __shfl_xor_sync(0xffffffffu, p, 1);
        p += __shfl_xor_sync(0xffffffffu, p, 2);
        p += __shfl_xor_sync(0xffffffffu, p, 4);
        float nm = fmaxf(m, p);
        float sc = __expf(m - nm);
        float al = __expf(p - nm);
        s = s * sc + al;
#pragma unroll
        for (int i = 0; i < VPL; i++) acc[i] = acc[i] * sc + al * xv[i];
        m = nm;
    }

    float inv = 1.f / s;
#pragma unroll
    for (int i = 0; i < VPL; i++) acc[i] *= inv;
    // reduce across the 4 head groups (head mean)
#pragma unroll
    for (int i = 0; i < VPL; i++) {
        acc[i] += __shfl_xor_sync(0xffffffffu, acc[i], 8);
        acc[i] += __shfl_xor_sync(0xffffffffu, acc[i], 16);
    }
    float u[VPL];
    const float* bp = bias + cl * VPL;
    float tot = 0.f;
#pragma unroll
    for (int i = 0; i < VPL; i++) { u[i] = acc[i] * 0.25f + bp[i]; tot += u[i]; }
#pragma unroll
    for (int off = 16; off >= 1; off >>= 1)
        tot += __shfl_xor_sync(0xffffffffu, tot, off);
    float mean = tot * (1.f / (4.f * C));
    float d[VPL], var = 0.f;
#pragma unroll
    for (int i = 0; i < VPL; i++) { d[i] = u[i] - mean; var += d[i] * d[i]; }
#pragma unroll
    for (int off = 16; off >= 1; off >>= 1)
        var += __shfl_xor_sync(0xffffffffu, var, off);
    float rstd = rsqrtf(var * (1.f / (4.f * C)) + 1e-5f);

    const float* gp = lng + cl * VPL;
    const float* b2 = lnb + cl * VPL;
    float y[VPL];
#pragma unroll
    for (int i = 0; i < VPL; i++)
        y[i] = fmaxf(d[i] * rstd * gp[i] + b2[i], 0.f);

    if (lane < 8) {
        if (FINAL) {
            int bg = batch[gw];
#pragma unroll
            for (int i = 0; i < VPL; i++)
                atomicAdd(&outp[bg * C + cl * VPL + i], y[i]);
        } else {
            float* op = outp + (size_t)gw * C + cl * VPL;
            *reinterpret_cast<float4*>(op)     = make_float4(y[0], y[1], y[2], y[3]);
            if (VPL == 8)
                *reinterpret_cast<float4*>(op + 4) = make_float4(y[4], y[5], y[6], y[7]);
        }
    }
}

// ---------------- divide pooled sums by graph sizes (binary search) ----
__global__ void div_kernel(const int* __restrict__ batch, float* __restrict__ out) {
    int t = threadIdx.x;
    if (t >= GG) return;
    int lo0 = 0, hi0 = NN;
    while (lo0 < hi0) { int mid = (lo0 + hi0) >> 1; if (batch[mid] < t) lo0 = mid + 1; else hi0 = mid; }
    int lo1 = lo0, hi1 = NN;
    while (lo1 < hi1) { int mid = (lo1 + hi1) >> 1; if (batch[mid] < t + 1) lo1 = mid + 1; else hi1 = mid; }
    float invc = 1.f / fmaxf((float)(lo1 - lo0), 1.f);
    float4* o4 = reinterpret_cast<float4*>(out + t * C2);
#pragma unroll
    for (int i = 0; i < C2 / 4; i++) {
        float4 v = o4[i];
        v.x *= invc; v.y *= invc; v.z *= invc; v.w *= invc;
        o4[i] = v;
    }
}

// ---------------- launch ----------------
extern "C" void kernel_launch(void* const* d_in, const int* in_sizes, int n_in,
                              void* d_out, int out_size) {
    const float* x     = (const float*)d_in[0];
    const int*   ei    = (const int*)  d_in[1];
    const int*   batch = (const int*)  d_in[2];
    const float* Wl1   = (const float*)d_in[3];
    const float* bl1   = (const float*)d_in[4];
    const float* Wr1   = (const float*)d_in[5];
    const float* br1   = (const float*)d_in[6];
    const float* att1  = (const float*)d_in[7];
    const float* b1    = (const float*)d_in[8];
    const float* ln1g  = (const float*)d_in[9];
    const float* ln1b  = (const float*)d_in[10];
    const float* Wl2   = (const float*)d_in[11];
    const float* bl2   = (const float*)d_in[12];
    const float* Wr2   = (const float*)d_in[13];
    const float* br2   = (const float*)d_in[14];
    const float* att2  = (const float*)d_in[15];
    const float* b2    = (const float*)d_in[16];
    const float* ln2g  = (const float*)d_in[17];
    const float* ln2b  = (const float*)d_in[18];
    float* out = (float*)d_out;

    __half* xl; float *xr, *h;
    cudaGetSymbolAddress((void**)&xl, g_xl);
    cudaGetSymbolAddress((void**)&xr, g_xr);
    cudaGetSymbolAddress((void**)&h,  g_h);

    zero_kernel <<<(NN + 255) / 256, 256>>>(out);
    count_kernel<<<(EE / 4 + 255) / 256, 256>>>(ei);
    scan_kernel <<<1, 1024>>>();
    fill_kernel <<<(ET / 4 + 255) / 256, 256>>>(ei);

    lin_kernel<INF_, 512><<<NN / 32, 512>>>(x, Wl1, bl1, Wr1, br1, xl, xr);
    gat_kernel<C1, false><<<NN / 8, 256>>>(xl, xr, att1, b1, ln1g, ln1b, batch, h);
    lin_kernel<C1, 256><<<NN / 32, 256>>>(h, Wl2, bl2, Wr2, br2, xl, xr);
    gat_kernel<C2, true><<<NN / 8, 256>>>(xl, xr, att2, b2, ln2g, ln2b, batch, out);

    div_kernel<<<1, 256>>>(batch, out);
}

// round 3
// speedup vs baseline: 1.3640x; 1.2243x over previous
#include <cuda_runtime.h>
#include <cuda_fp16.h>
#include <math.h>

// ---------------- problem constants ----------------
#define NN    20000
#define EE    400000
#define ET    (EE + NN)
#define GG    200
#define C1    64
#define C2    32
#define INF_  8

// ---------------- persistent scratch ----------------
__device__ __align__(16) __half g_xl[NN * 256];   // fp16 gathered message table
__device__ __align__(16) float  g_xr[NN * 256];   // fp32 query table
__device__ __align__(16) float  g_h [NN * 64];    // inter-layer activations
__device__ __align__(16) int    g_deg[NN];        // edge in-degree (no self loop)
__device__ __align__(16) int    g_pos[EE];        // slot of each edge within its row
__device__ __align__(16) int    g_rowptr[NN + 4];
__device__ int                  g_csr[ET];

// ---------------- CSR: count + record slot (single atomic pass) --------
__global__ void count_kernel(const int* __restrict__ ei) {
    int i = blockIdx.x * blockDim.x + threadIdx.x;
    if (i >= EE / 4) return;
    int4 d = reinterpret_cast<const int4*>(ei + EE)[i];
    int4 p;
    p.x = atomicAdd(&g_deg[d.x], 1);
    p.y = atomicAdd(&g_deg[d.y], 1);
    p.z = atomicAdd(&g_deg[d.z], 1);
    p.w = atomicAdd(&g_deg[d.w], 1);
    reinterpret_cast<int4*>(g_pos)[i] = p;
}

// ---------------- CSR: scan (single block, int4 I/O, +1 self loop) -----
__global__ void scan_kernel() {
    __shared__ int sbuf[1024];
    int t = threadIdx.x;
    int4 v[5];
    int s = 0;
    const int4* d4 = reinterpret_cast<const int4*>(g_deg);
    if (t < 1000) {
#pragma unroll
        for (int i = 0; i < 5; i++) {
            v[i] = d4[t * 5 + i];
            s += v[i].x + v[i].y + v[i].z + v[i].w + 4;   // +1 self loop each
        }
    }
    sbuf[t] = s;
    __syncthreads();
#pragma unroll
    for (int off = 1; off < 1024; off <<= 1) {
        int vv = (t >= off) ? sbuf[t - off] : 0;
        __syncthreads();
        sbuf[t] += vv;
        __syncthreads();
    }
    if (t < 1000) {
        int run = sbuf[t] - s;
        int4* rp4 = reinterpret_cast<int4*>(g_rowptr);
#pragma unroll
        for (int i = 0; i < 5; i++) {
            int4 o;
            o.x = run; run += v[i].x + 1;
            o.y = run; run += v[i].y + 1;
            o.z = run; run += v[i].z + 1;
            o.w = run; run += v[i].w + 1;
            rp4[t * 5 + i] = o;
        }
    }
    if (t == 1023) g_rowptr[NN] = sbuf[1023];
}

// ---------------- CSR: fill (atomic-free) ------------------------------
__global__ void fill_kernel(const int* __restrict__ ei) {
    int i = blockIdx.x * blockDim.x + threadIdx.x;
    if (i >= ET / 4) return;
    if (i < EE / 4) {
        int4 s4 = reinterpret_cast<const int4*>(ei)[i];
        int4 d4 = reinterpret_cast<const int4*>(ei + EE)[i];
        int4 p4 = reinterpret_cast<const int4*>(g_pos)[i];
        g_csr[g_rowptr[d4.x] + p4.x] = s4.x;
        g_csr[g_rowptr[d4.y] + p4.y] = s4.y;
        g_csr[g_rowptr[d4.z] + p4.z] = s4.z;
        g_csr[g_rowptr[d4.w] + p4.w] = s4.w;
    } else {
        int n = 4 * i - EE;                 // self loops -> last slot of row
#pragma unroll
        for (int j = 0; j < 4; j++)
            g_csr[g_rowptr[n + j] + g_deg[n + j]] = n + j;
    }
}

// ---------------- register-tiled linear; xl stored fp16, xr fp32 ------
template <int K, int DT>
__global__ void lin_kernel(const float* __restrict__ x,
                           const float* __restrict__ Wl, const float* __restrict__ bl,
                           const float* __restrict__ Wr, const float* __restrict__ br,
                           __half* __restrict__ xl, float* __restrict__ xr) {
    constexpr int DH = DT / 2;
    constexpr int MB = 32;
    constexpr int CT = DT / 4;
    __shared__ float xs[MB * K];
    int n0 = blockIdx.x * MB;
    int tid = threadIdx.x;
    for (int idx = tid; idx < MB * K; idx += blockDim.x)
        xs[idx] = x[n0 * K + idx];
    __syncthreads();

    int co  = tid % CT;
    int ro  = tid / CT;
    int col = co * 4;
    int r0  = ro * 8;
    bool left = (col < DH);
    const float* W    = left ? (Wl + col) : (Wr + col - DH);
    const float* bptr = left ? (bl + col) : (br + col - DH);
    float4 bv = *reinterpret_cast<const float4*>(bptr);
    float4 acc[8];
#pragma unroll
    for (int i = 0; i < 8; i++) acc[i] = bv;

#pragma unroll 8
    for (int k = 0; k < K; k++) {
        float4 w = *reinterpret_cast<const float4*>(W + k * DH);
#pragma unroll
        for (int i = 0; i < 8; i++) {
            float xv = xs[(r0 + i) * K + k];
            acc[i].x += xv * w.x;
            acc[i].y += xv * w.y;
            acc[i].z += xv * w.z;
            acc[i].w += xv * w.w;
        }
    }
    if (left) {
#pragma unroll
        for (int i = 0; i < 8; i++) {
            __half2* p = reinterpret_cast<__half2*>(xl + (size_t)(n0 + r0 + i) * DH + col);
            p[0] = __floats2half2_rn(acc[i].x, acc[i].y);
            p[1] = __floats2half2_rn(acc[i].z, acc[i].w);
        }
    } else {
        int oc = col - DH;
#pragma unroll
        for (int i = 0; i < 8; i++)
            *reinterpret_cast<float4*>(xr + (size_t)(n0 + r0 + i) * DH + oc) = acc[i];
    }
}

// ---------------- GATv2: warp per dst, half2 score, no-max softmax -----
// Lane L owns values [L*VPL, L*VPL+VPL) of the D=4C row; head = L/8.
template <int C, bool FINAL>
__global__ void gat_kernel(const __half* __restrict__ xl, const float* __restrict__ xr,
                           const float* __restrict__ att, const float* __restrict__ bias,
                           const float* __restrict__ lng, const float* __restrict__ lnb,
                           const int* __restrict__ batch, float* __restrict__ outp) {
    constexpr int D   = 4 * C;
    constexpr int VPL = C / 8;
    constexpr int H2  = VPL / 2;
    int gw = (blockIdx.x * blockDim.x + threadIdx.x) >> 5;
    if (gw >= NN) return;
    int lane = threadIdx.x & 31;
    int h  = lane >> 3;
    int cl = lane & 7;

    __half2 a2[H2], q2[H2];
    const float* attp = att + h * C + cl * VPL;
    const float* qp   = xr + gw * D + lane * VPL;
#pragma unroll
    for (int i = 0; i < H2; i++) {
        a2[i] = __floats2half2_rn(attp[2 * i], attp[2 * i + 1]);
        q2[i] = __floats2half2_rn(qp[2 * i],  qp[2 * i + 1]);
    }
    float acc[VPL];
#pragma unroll
    for (int i = 0; i < VPL; i++) acc[i] = 0.f;
    float s = 0.f;

    const __half2 c02 = __floats2half2_rn(0.2f, 0.2f);
    const __half* rowp = xl + lane * VPL;

    auto do_edge = [&](__half2* hv) {
        __half2 p2 = __floats2half2_rn(0.f, 0.f);
#pragma unroll
        for (int i = 0; i < H2; i++) {
            __half2 v  = __hadd2(hv[i], q2[i]);
            __half2 lr = __hmax2(v, __hmul2(v, c02));
            p2 = __hfma2(a2[i], lr, p2);
        }
#pragma unroll
        for (int off = 1; off < 8; off <<= 1) {
            unsigned pu = __shfl_xor_sync(0xffffffffu,
                          *reinterpret_cast<unsigned*>(&p2), off);
            p2 = __hadd2(p2, *reinterpret_cast<__half2*>(&pu));
        }
        float2 pf = __half22float2(p2);
        float al = __expf(pf.x + pf.y);      // |score| small: no max needed
        s += al;
#pragma unroll
        for (int i = 0; i < H2; i++) {
            float2 f = __half22float2(hv[i]);
            acc[2 * i]     += al * f.x;
            acc[2 * i + 1] += al * f.y;
        }
    };

    auto loadv = [&](__half2* hv, int src) {
        if (C == 64) {
            uint4 u = *reinterpret_cast<const uint4*>(rowp + src * D);
            *reinterpret_cast<uint4*>(hv) = u;
        } else {
            uint2 u = *reinterpret_cast<const uint2*>(rowp + src * D);
            *reinterpret_cast<uint2*>(hv) = u;
        }
    };

    int kb = g_rowptr[gw], ke = g_rowptr[gw + 1];
    int k = kb;
    for (; k + 4 <= ke; k += 4) {
        int i0 = g_csr[k], i1 = g_csr[k + 1], i2 = g_csr[k + 2], i3 = g_csr[k + 3];
        __half2 hv0[H2], hv1[H2], hv2[H2], hv3[H2];
        loadv(hv0, i0); loadv(hv1, i1); loadv(hv2, i2); loadv(hv3, i3);
        do_edge(hv0); do_edge(hv1); do_edge(hv2); do_edge(hv3);
    }
    for (; k < ke; k++) {
        __half2 hv[H2];
        loadv(hv, g_csr[k]);
        do_edge(hv);
    }

    float inv = 1.f / s;
#pragma unroll
    for (int i = 0; i < VPL; i++) acc[i] *= inv;
    // head mean: reduce across the 4 head groups
#pragma unroll
    for (int i = 0; i < VPL; i++) {
        acc[i] += __shfl_xor_sync(0xffffffffu, acc[i], 8);
        acc[i] += __shfl_xor_sync(0xffffffffu, acc[i], 16);
    }
    float u[VPL];
    const float* bp = bias + cl * VPL;
    float tot = 0.f;
#pragma unroll
    for (int i = 0; i < VPL; i++) { u[i] = acc[i] * 0.25f + bp[i]; tot += u[i]; }
#pragma unroll
    for (int off = 16; off >= 1; off >>= 1)
        tot += __shfl_xor_sync(0xffffffffu, tot, off);
    float mean = tot * (1.f / (4.f * C));
    float d[VPL], var = 0.f;
#pragma unroll
    for (int i = 0; i < VPL; i++) { d[i] = u[i] - mean; var += d[i] * d[i]; }
#pragma unroll
    for (int off = 16; off >= 1; off >>= 1)
        var += __shfl_xor_sync(0xffffffffu, var, off);
    float rstd = rsqrtf(var * (1.f / (4.f * C)) + 1e-5f);

    const float* gp = lng + cl * VPL;
    const float* b2 = lnb + cl * VPL;
    float y[VPL];
#pragma unroll
    for (int i = 0; i < VPL; i++)
        y[i] = fmaxf(d[i] * rstd * gp[i] + b2[i], 0.f);

    if (lane < 8) {
        if (FINAL) {
            int bg = batch[gw];
#pragma unroll
            for (int i = 0; i < VPL; i++)
                atomicAdd(&outp[bg * C + cl * VPL + i], y[i]);
        } else {
            float* op = outp + gw * C + cl * VPL;
            *reinterpret_cast<float4*>(op) = make_float4(y[0], y[1], y[2], y[3]);
            if (VPL == 8)
                *reinterpret_cast<float4*>(op + 4) = make_float4(y[4], y[5], y[6], y[7]);
        }
    }
}

// ---------------- divide pooled sums by graph size (binary search) -----
__global__ void div_kernel(const int* __restrict__ batch, float* __restrict__ out) {
    int t = threadIdx.x;
    if (t >= GG) return;
    int lo0 = 0, hi0 = NN;
    while (lo0 < hi0) { int mid = (lo0 + hi0) >> 1; if (batch[mid] < t) lo0 = mid + 1; else hi0 = mid; }
    int lo1 = lo0, hi1 = NN;
    while (lo1 < hi1) { int mid = (lo1 + hi1) >> 1; if (batch[mid] < t + 1) lo1 = mid + 1; else hi1 = mid; }
    float invc = 1.f / fmaxf((float)(lo1 - lo0), 1.f);
    float4* o4 = reinterpret_cast<float4*>(out + t * C2);
#pragma unroll
    for (int i = 0; i < C2 / 4; i++) {
        float4 v = o4[i];
        v.x *= invc; v.y *= invc; v.z *= invc; v.w *= invc;
        o4[i] = v;
    }
}

// ---------------- launch ----------------
extern "C" void kernel_launch(void* const* d_in, const int* in_sizes, int n_in,
                              void* d_out, int out_size) {
    const float* x     = (const float*)d_in[0];
    const int*   ei    = (const int*)  d_in[1];
    const int*   batch = (const int*)  d_in[2];
    const float* Wl1   = (const float*)d_in[3];
    const float* bl1   = (const float*)d_in[4];
    const float* Wr1   = (const float*)d_in[5];
    const float* br1   = (const float*)d_in[6];
    const float* att1  = (const float*)d_in[7];
    const float* b1    = (const float*)d_in[8];
    const float* ln1g  = (const float*)d_in[9];
    const float* ln1b  = (const float*)d_in[10];
    const float* Wl2   = (const float*)d_in[11];
    const float* bl2   = (const float*)d_in[12];
    const float* Wr2   = (const float*)d_in[13];
    const float* br2   = (const float*)d_in[14];
    const float* att2  = (const float*)d_in[15];
    const float* b2    = (const float*)d_in[16];
    const float* ln2g  = (const float*)d_in[17];
    const float* ln2b  = (const float*)d_in[18];
    float* out = (float*)d_out;

    __half* xl; float *xr, *h; int* degp;
    cudaGetSymbolAddress((void**)&xl,   g_xl);
    cudaGetSymbolAddress((void**)&xr,   g_xr);
    cudaGetSymbolAddress((void**)&h,    g_h);
    cudaGetSymbolAddress((void**)&degp, g_deg);

    cudaMemsetAsync(degp, 0, NN * sizeof(int));
    cudaMemsetAsync(out,  0, GG * C2 * sizeof(float));

    count_kernel<<<(EE / 4 + 255) / 256, 256>>>(ei);
    scan_kernel <<<1, 1024>>>();
    fill_kernel <<<(ET / 4 + 255) / 256, 256>>>(ei);

    lin_kernel<INF_, 512><<<NN / 32, 512>>>(x, Wl1, bl1, Wr1, br1, xl, xr);
    gat_kernel<C1, false><<<NN / 8, 256>>>(xl, xr, att1, b1, ln1g, ln1b, batch, h);
    lin_kernel<C1, 256><<<NN / 32, 256>>>(h, Wl2, bl2, Wr2, br2, xl, xr);
    gat_kernel<C2, true><<<NN / 8, 256>>>(xl, xr, att2, b2, ln2g, ln2b, batch, out);

    div_kernel<<<1, 256>>>(batch, out);
}

// round 4
// speedup vs baseline: 1.4242x; 1.0441x over previous
#include <cuda_runtime.h>
#include <cuda_fp16.h>
#include <math.h>

// ---------------- problem constants ----------------
#define NN    20000
#define EE    400000
#define ET    (EE + NN)
#define GG    200
#define C1    64
#define C2    32

// ---------------- persistent scratch ----------------
__device__ __align__(16) __half   g_xl[NN * 256];   // fp16 message table
__device__ __align__(16) float    g_xr[NN * 256];   // fp32 query table
__device__ __align__(16) float    g_h [NN * 64];    // inter-layer activations
__device__ __align__(16) __half2  g_w2h[32 * 256];  // packed layer-2 weights
__device__ __align__(16) int      g_deg[NN];
__device__ __align__(16) int      g_pos[EE];
__device__ __align__(16) int      g_rowptr[NN + 4];
__device__ int                    g_csr[ET];

// ---------------- pack layer-2 weights: w2h[kp][c] = {W[2kp][c],W[2kp+1][c]}
__global__ void prep_w2_kernel(const float* __restrict__ Wl2, const float* __restrict__ Wr2) {
    int i = blockIdx.x * blockDim.x + threadIdx.x;
    if (i >= 32 * 256) return;
    int kp = i >> 8, c = i & 255;
    float a, b;
    if (c < 128) { a = Wl2[(2 * kp) * 128 + c];       b = Wl2[(2 * kp + 1) * 128 + c]; }
    else         { a = Wr2[(2 * kp) * 128 + c - 128]; b = Wr2[(2 * kp + 1) * 128 + c - 128]; }
    g_w2h[i] = __floats2half2_rn(a, b);
}

// ---------------- CSR: count + record slot ----------------
__global__ void count_kernel(const int* __restrict__ ei) {
    int i = blockIdx.x * blockDim.x + threadIdx.x;
    if (i >= EE / 4) return;
    int4 d = reinterpret_cast<const int4*>(ei + EE)[i];
    int4 p;
    p.x = atomicAdd(&g_deg[d.x], 1);
    p.y = atomicAdd(&g_deg[d.y], 1);
    p.z = atomicAdd(&g_deg[d.z], 1);
    p.w = atomicAdd(&g_deg[d.w], 1);
    reinterpret_cast<int4*>(g_pos)[i] = p;
}

// ---------------- CSR: scan ----------------
__global__ void scan_kernel() {
    __shared__ int sbuf[1024];
    int t = threadIdx.x;
    int4 v[5];
    int s = 0;
    const int4* d4 = reinterpret_cast<const int4*>(g_deg);
    if (t < 1000) {
#pragma unroll
        for (int i = 0; i < 5; i++) {
            v[i] = d4[t * 5 + i];
            s += v[i].x + v[i].y + v[i].z + v[i].w + 4;
        }
    }
    sbuf[t] = s;
    __syncthreads();
#pragma unroll
    for (int off = 1; off < 1024; off <<= 1) {
        int vv = (t >= off) ? sbuf[t - off] : 0;
        __syncthreads();
        sbuf[t] += vv;
        __syncthreads();
    }
    if (t < 1000) {
        int run = sbuf[t] - s;
        int4* rp4 = reinterpret_cast<int4*>(g_rowptr);
#pragma unroll
        for (int i = 0; i < 5; i++) {
            int4 o;
            o.x = run; run += v[i].x + 1;
            o.y = run; run += v[i].y + 1;
            o.z = run; run += v[i].z + 1;
            o.w = run; run += v[i].w + 1;
            rp4[t * 5 + i] = o;
        }
    }
    if (t == 1023) g_rowptr[NN] = sbuf[1023];
}

// ---------------- CSR: fill (atomic-free) ----------------
__global__ void fill_kernel(const int* __restrict__ ei) {
    int i = blockIdx.x * blockDim.x + threadIdx.x;
    if (i >= ET / 4) return;
    if (i < EE / 4) {
        int4 s4 = reinterpret_cast<const int4*>(ei)[i];
        int4 d4 = reinterpret_cast<const int4*>(ei + EE)[i];
        int4 p4 = reinterpret_cast<const int4*>(g_pos)[i];
        g_csr[g_rowptr[d4.x] + p4.x] = s4.x;
        g_csr[g_rowptr[d4.y] + p4.y] = s4.y;
        g_csr[g_rowptr[d4.z] + p4.z] = s4.z;
        g_csr[g_rowptr[d4.w] + p4.w] = s4.w;
    } else {
        int n = 4 * i - EE;
#pragma unroll
        for (int j = 0; j < 4; j++)
            g_csr[g_rowptr[n + j] + g_deg[n + j]] = n + j;
    }
}

// ---------------- layer-1 linear: K=8, DT=512, 4-row tile ----------------
__global__ void __launch_bounds__(512, 3)
lin1_kernel(const float* __restrict__ x,
            const float* __restrict__ Wl, const float* __restrict__ bl,
            const float* __restrict__ Wr, const float* __restrict__ br,
            __half* __restrict__ xl, float* __restrict__ xr) {
    __shared__ float xs[16 * 8];
    int n0 = blockIdx.x * 16;
    int tid = threadIdx.x;
    if (tid < 32)
        reinterpret_cast<float4*>(xs)[tid] =
            reinterpret_cast<const float4*>(x + n0 * 8)[tid];
    __syncthreads();

    int co = tid & 127;
    int r0 = (tid >> 7) * 4;
    int col = co * 4;
    bool left = (col < 256);
    const float* W    = left ? (Wl + col) : (Wr + col - 256);
    const float* bptr = left ? (bl + col) : (br + col - 256);
    float4 bv = *reinterpret_cast<const float4*>(bptr);
    float4 acc[4];
#pragma unroll
    for (int i = 0; i < 4; i++) acc[i] = bv;

#pragma unroll
    for (int k = 0; k < 8; k++) {
        float4 w = *reinterpret_cast<const float4*>(W + k * 256);
#pragma unroll
        for (int i = 0; i < 4; i++) {
            float xv = xs[(r0 + i) * 8 + k];
            acc[i].x += xv * w.x;
            acc[i].y += xv * w.y;
            acc[i].z += xv * w.z;
            acc[i].w += xv * w.w;
        }
    }
    if (left) {
#pragma unroll
        for (int i = 0; i < 4; i++) {
            __half2* p = reinterpret_cast<__half2*>(xl + (n0 + r0 + i) * 256 + col);
            p[0] = __floats2half2_rn(acc[i].x, acc[i].y);
            p[1] = __floats2half2_rn(acc[i].z, acc[i].w);
        }
    } else {
        int oc = col - 256;
#pragma unroll
        for (int i = 0; i < 4; i++)
            *reinterpret_cast<float4*>(xr + (n0 + r0 + i) * 256 + oc) = acc[i];
    }
}

// ---------------- layer-2 linear: K=64, DT=256, half2 split-K ----------------
__global__ void __launch_bounds__(512, 2)
lin2_kernel(const float* __restrict__ xin,
            const float* __restrict__ bl, const float* __restrict__ br,
            __half* __restrict__ xl, float* __restrict__ xr) {
    __shared__ __half2 xs2[32 * 32];      // [row][kp] = {x[2kp], x[2kp+1]}
    int n0 = blockIdx.x * 32;
    int tid = threadIdx.x;
    for (int idx = tid; idx < 32 * 32; idx += 512) {
        int row = idx >> 5, kp = idx & 31;
        float2 v = *reinterpret_cast<const float2*>(xin + (n0 + row) * 64 + 2 * kp);
        xs2[idx] = __floats2half2_rn(v.x, v.y);
    }
    __syncthreads();

    int co = tid & 63;
    int r0 = (tid >> 6) * 4;
    int col = co * 4;
    bool left = (col < 128);
    const float* bptr = left ? (bl + col) : (br + col - 128);
    float4 bv = *reinterpret_cast<const float4*>(bptr);
    float4 accf[4];
#pragma unroll
    for (int i = 0; i < 4; i++) accf[i] = bv;

    const __half2* wp = g_w2h + co * 4;
#pragma unroll
    for (int ch = 0; ch < 2; ch++) {
        __half2 ah[4][4];
#pragma unroll
        for (int r = 0; r < 4; r++)
#pragma unroll
            for (int c = 0; c < 4; c++) ah[r][c] = __floats2half2_rn(0.f, 0.f);
#pragma unroll
        for (int kp = 0; kp < 16; kp++) {
            int kk = ch * 16 + kp;
            uint4 wv = *reinterpret_cast<const uint4*>(wp + kk * 256);
            __half2 w0 = *reinterpret_cast<__half2*>(&wv.x);
            __half2 w1 = *reinterpret_cast<__half2*>(&wv.y);
            __half2 w2 = *reinterpret_cast<__half2*>(&wv.z);
            __half2 w3 = *reinterpret_cast<__half2*>(&wv.w);
#pragma unroll
            for (int r = 0; r < 4; r++) {
                __half2 xp = xs2[(r0 + r) * 32 + kk];
                ah[r][0] = __hfma2(xp, w0, ah[r][0]);
                ah[r][1] = __hfma2(xp, w1, ah[r][1]);
                ah[r][2] = __hfma2(xp, w2, ah[r][2]);
                ah[r][3] = __hfma2(xp, w3, ah[r][3]);
            }
        }
#pragma unroll
        for (int r = 0; r < 4; r++) {
            float2 f;
            f = __half22float2(ah[r][0]); accf[r].x += f.x + f.y;
            f = __half22float2(ah[r][1]); accf[r].y += f.x + f.y;
            f = __half22float2(ah[r][2]); accf[r].z += f.x + f.y;
            f = __half22float2(ah[r][3]); accf[r].w += f.x + f.y;
        }
    }

    if (left) {
#pragma unroll
        for (int i = 0; i < 4; i++) {
            __half2* p = reinterpret_cast<__half2*>(xl + (n0 + r0 + i) * 128 + col);
            p[0] = __floats2half2_rn(accf[i].x, accf[i].y);
            p[1] = __floats2half2_rn(accf[i].z, accf[i].w);
        }
    } else {
        int oc = col - 128;
#pragma unroll
        for (int i = 0; i < 4; i++)
            *reinterpret_cast<float4*>(xr + (n0 + r0 + i) * 128 + oc) = accf[i];
    }
}

// ---------------- GATv2: warp per dst, half2 score, no-max softmax -----
template <int C, bool FINAL>
__global__ void gat_kernel(const __half* __restrict__ xl, const float* __restrict__ xr,
                           const float* __restrict__ att, const float* __restrict__ bias,
                           const float* __restrict__ lng, const float* __restrict__ lnb,
                           const int* __restrict__ batch, float* __restrict__ outp) {
    constexpr int D   = 4 * C;
    constexpr int VPL = C / 8;
    constexpr int H2  = VPL / 2;
    int gw = blockIdx.x * 2 + (threadIdx.x >> 5);
    if (gw >= NN) return;
    int lane = threadIdx.x & 31;
    int h  = lane >> 3;
    int cl = lane & 7;

    __half2 a2[H2], q2[H2];
    const float* attp = att + h * C + cl * VPL;
    const float* qp   = xr + gw * D + lane * VPL;
#pragma unroll
    for (int i = 0; i < H2; i++) {
        a2[i] = __floats2half2_rn(attp[2 * i] * 1.44269504f,
                                  attp[2 * i + 1] * 1.44269504f);
        q2[i] = __floats2half2_rn(qp[2 * i], qp[2 * i + 1]);
    }
    float acc[VPL];
#pragma unroll
    for (int i = 0; i < VPL; i++) acc[i] = 0.f;
    float s = 0.f;

    const __half2 c02 = __floats2half2_rn(0.2f, 0.2f);
    const __half* rowp = xl + lane * VPL;

    auto do_edge = [&](__half2* hv) {
        __half2 p2 = __floats2half2_rn(0.f, 0.f);
#pragma unroll
        for (int i = 0; i < H2; i++) {
            __half2 v  = __hadd2(hv[i], q2[i]);
            __half2 lr = __hmax2(v, __hmul2(v, c02));
            p2 = __hfma2(a2[i], lr, p2);
        }
#pragma unroll
        for (int off = 1; off < 8; off <<= 1) {
            unsigned pu = __shfl_xor_sync(0xffffffffu,
                          *reinterpret_cast<unsigned*>(&p2), off);
            p2 = __hadd2(p2, *reinterpret_cast<__half2*>(&pu));
        }
        float2 pf = __half22float2(p2);
        float al = exp2f(pf.x + pf.y);       // att pre-scaled by log2(e)
        s += al;
#pragma unroll
        for (int i = 0; i < H2; i++) {
            float2 f = __half22float2(hv[i]);
            acc[2 * i]     += al * f.x;
            acc[2 * i + 1] += al * f.y;
        }
    };

    auto loadv = [&](__half2* hv, int src) {
        if (C == 64)
            *reinterpret_cast<uint4*>(hv) = *reinterpret_cast<const uint4*>(rowp + src * D);
        else
            *reinterpret_cast<uint2*>(hv) = *reinterpret_cast<const uint2*>(rowp + src * D);
    };

    int kb = g_rowptr[gw], ke = g_rowptr[gw + 1];
    int k = kb;
    for (; k + 4 <= ke; k += 4) {
        int i0 = g_csr[k], i1 = g_csr[k + 1], i2 = g_csr[k + 2], i3 = g_csr[k + 3];
        __half2 hv0[H2], hv1[H2], hv2[H2], hv3[H2];
        loadv(hv0, i0); loadv(hv1, i1); loadv(hv2, i2); loadv(hv3, i3);
        do_edge(hv0); do_edge(hv1); do_edge(hv2); do_edge(hv3);
    }
    for (; k < ke; k++) {
        __half2 hv[H2];
        loadv(hv, g_csr[k]);
        do_edge(hv);
    }

    float inv = 1.f / s;
#pragma unroll
    for (int i = 0; i < VPL; i++) acc[i] *= inv;
#pragma unroll
    for (int i = 0; i < VPL; i++) {
        acc[i] += __shfl_xor_sync(0xffffffffu, acc[i], 8);
        acc[i] += __shfl_xor_sync(0xffffffffu, acc[i], 16);
    }
    float u[VPL];
    const float* bp = bias + cl * VPL;
    float tot = 0.f;
#pragma unroll
    for (int i = 0; i < VPL; i++) { u[i] = acc[i] * 0.25f + bp[i]; tot += u[i]; }
#pragma unroll
    for (int off = 16; off >= 1; off >>= 1)
        tot += __shfl_xor_sync(0xffffffffu, tot, off);
    float mean = tot * (1.f / (4.f * C));
    float d[VPL], var = 0.f;
#pragma unroll
    for (int i = 0; i < VPL; i++) { d[i] = u[i] - mean; var += d[i] * d[i]; }
#pragma unroll
    for (int off = 16; off >= 1; off >>= 1)
        var += __shfl_xor_sync(0xffffffffu, var, off);
    float rstd = rsqrtf(var * (1.f / (4.f * C)) + 1e-5f);

    const float* gp = lng + cl * VPL;
    const float* b2 = lnb + cl * VPL;
    float y[VPL];
#pragma unroll
    for (int i = 0; i < VPL; i++)
        y[i] = fmaxf(d[i] * rstd * gp[i] + b2[i], 0.f);

    if (lane < 8) {
        if (FINAL) {
            int bg = batch[gw];
#pragma unroll
            for (int i = 0; i < VPL; i++)
                atomicAdd(&outp[bg * C + cl * VPL + i], y[i]);
        } else {
            float* op = outp + gw * C + cl * VPL;
            *reinterpret_cast<float4*>(op) = make_float4(y[0], y[1], y[2], y[3]);
            if (VPL == 8)
                *reinterpret_cast<float4*>(op + 4) = make_float4(y[4], y[5], y[6], y[7]);
        }
    }
}

// ---------------- divide pooled sums by graph size ----------------
__global__ void div_kernel(const int* __restrict__ batch, float* __restrict__ out) {
    int t = threadIdx.x;
    if (t >= GG) return;
    int lo0 = 0, hi0 = NN;
    while (lo0 < hi0) { int mid = (lo0 + hi0) >> 1; if (batch[mid] < t) lo0 = mid + 1; else hi0 = mid; }
    int lo1 = lo0, hi1 = NN;
    while (lo1 < hi1) { int mid = (lo1 + hi1) >> 1; if (batch[mid] < t + 1) lo1 = mid + 1; else hi1 = mid; }
    float invc = 1.f / fmaxf((float)(lo1 - lo0), 1.f);
    float4* o4 = reinterpret_cast<float4*>(out + t * C2);
#pragma unroll
    for (int i = 0; i < C2 / 4; i++) {
        float4 v = o4[i];
        v.x *= invc; v.y *= invc; v.z *= invc; v.w *= invc;
        o4[i] = v;
    }
}

// ---------------- launch ----------------
extern "C" void kernel_launch(void* const* d_in, const int* in_sizes, int n_in,
                              void* d_out, int out_size) {
    const float* x     = (const float*)d_in[0];
    const int*   ei    = (const int*)  d_in[1];
    const int*   batch = (const int*)  d_in[2];
    const float* Wl1   = (const float*)d_in[3];
    const float* bl1   = (const float*)d_in[4];
    const float* Wr1   = (const float*)d_in[5];
    const float* br1   = (const float*)d_in[6];
    const float* att1  = (const float*)d_in[7];
    const float* b1    = (const float*)d_in[8];
    const float* ln1g  = (const float*)d_in[9];
    const float* ln1b  = (const float*)d_in[10];
    const float* Wl2   = (const float*)d_in[11];
    const float* bl2   = (const float*)d_in[12];
    const float* Wr2   = (const float*)d_in[13];
    const float* br2   = (const float*)d_in[14];
    const float* att2  = (const float*)d_in[15];
    const float* b2    = (const float*)d_in[16];
    const float* ln2g  = (const float*)d_in[17];
    const float* ln2b  = (const float*)d_in[18];
    float* out = (float*)d_out;

    __half* xl; float *xr, *h; int* degp;
    cudaGetSymbolAddress((void**)&xl,   g_xl);
    cudaGetSymbolAddress((void**)&xr,   g_xr);
    cudaGetSymbolAddress((void**)&h,    g_h);
    cudaGetSymbolAddress((void**)&degp, g_deg);

    cudaMemsetAsync(degp, 0, NN * sizeof(int));
    cudaMemsetAsync(out,  0, GG * C2 * sizeof(float));

    prep_w2_kernel<<<32, 256>>>(Wl2, Wr2);
    count_kernel<<<(EE / 4 + 255) / 256, 256>>>(ei);
    scan_kernel <<<1, 1024>>>();
    fill_kernel <<<(ET / 4 + 255) / 256, 256>>>(ei);

    lin1_kernel<<<NN / 16, 512>>>(x, Wl1, bl1, Wr1, br1, xl, xr);
    gat_kernel<C1, false><<<NN / 2, 64>>>(xl, xr, att1, b1, ln1g, ln1b, batch, h);
    lin2_kernel<<<NN / 32, 512>>>(h, bl2, br2, xl, xr);
    gat_kernel<C2, true><<<NN / 2, 64>>>(xl, xr, att2, b2, ln2g, ln2b, batch, out);

    div_kernel<<<1, 256>>>(batch, out);
}

// round 5
// speedup vs baseline: 1.4936x; 1.0488x over previous
#include <cuda_runtime.h>
#include <cuda_fp16.h>
#include <math.h>

// ---------------- problem constants ----------------
#define NN    20000
#define EE    400000
#define ET    (EE + NN)
#define GG    200
#define C1    64
#define C2    32

// ---------------- persistent scratch ----------------
__device__ __align__(16) __half   g_xl[NN * 256];   // fp16 message table
__device__ __align__(16) float    g_xr[NN * 256];   // fp32 query table
__device__ __align__(16) float    g_h [NN * 64];    // inter-layer activations
__device__ __align__(16) __half2  g_w2h[32 * 256];  // packed layer-2 weights
__device__ __align__(16) int      g_deg[NN];
__device__ __align__(16) int      g_pos[EE];
__device__ __align__(16) int      g_rowptr[NN + 4];
__device__ int                    g_csr[ET];

// ---------------- kernel 1: count (+slot record) fused with w2 pack ----
#define CNT_BLK 391                       // ceil(EE/4/256)
__global__ void countprep_kernel(const int* __restrict__ ei,
                                 const float* __restrict__ Wl2,
                                 const float* __restrict__ Wr2) {
    if (blockIdx.x < CNT_BLK) {
        int i = blockIdx.x * blockDim.x + threadIdx.x;
        if (i >= EE / 4) return;
        int4 d = reinterpret_cast<const int4*>(ei + EE)[i];
        int4 p;
        p.x = atomicAdd(&g_deg[d.x], 1);
        p.y = atomicAdd(&g_deg[d.y], 1);
        p.z = atomicAdd(&g_deg[d.z], 1);
        p.w = atomicAdd(&g_deg[d.w], 1);
        reinterpret_cast<int4*>(g_pos)[i] = p;
    } else {
        int i = (blockIdx.x - CNT_BLK) * blockDim.x + threadIdx.x;
        if (i >= 32 * 256) return;
        int kp = i >> 8, c = i & 255;
        float a, b;
        if (c < 128) { a = Wl2[(2 * kp) * 128 + c];       b = Wl2[(2 * kp + 1) * 128 + c]; }
        else         { a = Wr2[(2 * kp) * 128 + c - 128]; b = Wr2[(2 * kp + 1) * 128 + c - 128]; }
        g_w2h[i] = __floats2half2_rn(a, b);
    }
}

// ---------------- kernel 2: scan ----------------
__global__ void scan_kernel() {
    __shared__ int sbuf[1024];
    int t = threadIdx.x;
    int4 v[5];
    int s = 0;
    const int4* d4 = reinterpret_cast<const int4*>(g_deg);
    if (t < 1000) {
#pragma unroll
        for (int i = 0; i < 5; i++) {
            v[i] = d4[t * 5 + i];
            s += v[i].x + v[i].y + v[i].z + v[i].w + 4;
        }
    }
    sbuf[t] = s;
    __syncthreads();
#pragma unroll
    for (int off = 1; off < 1024; off <<= 1) {
        int vv = (t >= off) ? sbuf[t - off] : 0;
        __syncthreads();
        sbuf[t] += vv;
        __syncthreads();
    }
    if (t < 1000) {
        int run = sbuf[t] - s;
        int4* rp4 = reinterpret_cast<int4*>(g_rowptr);
#pragma unroll
        for (int i = 0; i < 5; i++) {
            int4 o;
            o.x = run; run += v[i].x + 1;
            o.y = run; run += v[i].y + 1;
            o.z = run; run += v[i].z + 1;
            o.w = run; run += v[i].w + 1;
            rp4[t * 5 + i] = o;
        }
    }
    if (t == 1023) g_rowptr[NN] = sbuf[1023];
}

// ---------------- kernel 3: fill (1 edge/thread) fused with lin1 -------
#define FILL_BLK 1641                     // ceil(ET/256)
__global__ void __launch_bounds__(256, 6)
filllin1_kernel(const int* __restrict__ ei,
                const float* __restrict__ x,
                const float* __restrict__ Wl, const float* __restrict__ bl,
                const float* __restrict__ Wr, const float* __restrict__ br,
                __half* __restrict__ xl, float* __restrict__ xr) {
    if (blockIdx.x < FILL_BLK) {
        int i = blockIdx.x * blockDim.x + threadIdx.x;
        if (i >= ET) return;
        if (i < EE) {
            int src = ei[i];
            int dst = ei[EE + i];
            int pos = g_pos[i];
            g_csr[g_rowptr[dst] + pos] = src;
        } else {
            int n = i - EE;                // self loop -> last slot of row
            g_csr[g_rowptr[n] + g_deg[n]] = n;
        }
        return;
    }
    // ---- lin1: 8 rows per block, 256 threads ----
    __shared__ float xs[8 * 8];
    int n0 = (blockIdx.x - FILL_BLK) * 8;
    int tid = threadIdx.x;
    if (tid < 16)
        reinterpret_cast<float4*>(xs)[tid] =
            reinterpret_cast<const float4*>(x + n0 * 8)[tid];
    __syncthreads();

    int co = tid & 127;
    int r0 = (tid >> 7) * 4;
    int col = co * 4;
    bool left = (col < 256);
    const float* W    = left ? (Wl + col) : (Wr + col - 256);
    const float* bptr = left ? (bl + col) : (br + col - 256);
    float4 bv = *reinterpret_cast<const float4*>(bptr);
    float4 acc[4];
#pragma unroll
    for (int i = 0; i < 4; i++) acc[i] = bv;

#pragma unroll
    for (int k = 0; k < 8; k++) {
        float4 w = *reinterpret_cast<const float4*>(W + k * 256);
#pragma unroll
        for (int i = 0; i < 4; i++) {
            float xv = xs[(r0 + i) * 8 + k];
            acc[i].x += xv * w.x;
            acc[i].y += xv * w.y;
            acc[i].z += xv * w.z;
            acc[i].w += xv * w.w;
        }
    }
    if (left) {
#pragma unroll
        for (int i = 0; i < 4; i++) {
            __half2* p = reinterpret_cast<__half2*>(xl + (n0 + r0 + i) * 256 + col);
            p[0] = __floats2half2_rn(acc[i].x, acc[i].y);
            p[1] = __floats2half2_rn(acc[i].z, acc[i].w);
        }
    } else {
        int oc = col - 256;
#pragma unroll
        for (int i = 0; i < 4; i++)
            *reinterpret_cast<float4*>(xr + (n0 + r0 + i) * 256 + oc) = acc[i];
    }
}

// ---------------- kernel 4: GATv2 (warp/dst, batched scores) ----------
template <int C, bool FINAL>
__global__ void gat_kernel(const __half* __restrict__ xl, const float* __restrict__ xr,
                           const float* __restrict__ att, const float* __restrict__ bias,
                           const float* __restrict__ lng, const float* __restrict__ lnb,
                           const int* __restrict__ batch, float* __restrict__ outp) {
    constexpr int D   = 4 * C;
    constexpr int VPL = C / 8;
    constexpr int H2  = VPL / 2;
    int gw = blockIdx.x * 4 + (threadIdx.x >> 5);
    if (gw >= NN) return;
    int lane = threadIdx.x & 31;
    int h  = lane >> 3;
    int cl = lane & 7;

    __half2 a2[H2], q2[H2];
    const float* attp = att + h * C + cl * VPL;
    const float* qp   = xr + gw * D + lane * VPL;
#pragma unroll
    for (int i = 0; i < H2; i++) {
        a2[i] = __floats2half2_rn(attp[2 * i] * 1.44269504f,
                                  attp[2 * i + 1] * 1.44269504f);
        q2[i] = __floats2half2_rn(qp[2 * i], qp[2 * i + 1]);
    }
    float acc[VPL];
#pragma unroll
    for (int i = 0; i < VPL; i++) acc[i] = 0.f;
    float s = 0.f;

    const __half2 c02 = __floats2half2_rn(0.2f, 0.2f);
    const __half* rowp = xl + lane * VPL;

    auto loadv = [&](__half2* hv, int src) {
        if (C == 64)
            *reinterpret_cast<uint4*>(hv) = *reinterpret_cast<const uint4*>(rowp + src * D);
        else
            *reinterpret_cast<uint2*>(hv) = *reinterpret_cast<const uint2*>(rowp + src * D);
    };
    auto score = [&](__half2* hv) -> __half2 {
        __half2 p2 = __floats2half2_rn(0.f, 0.f);
#pragma unroll
        for (int i = 0; i < H2; i++) {
            __half2 v  = __hadd2(hv[i], q2[i]);
            __half2 lr = __hmax2(v, __hmul2(v, c02));
            p2 = __hfma2(a2[i], lr, p2);
        }
        return p2;
    };

    int kb = g_rowptr[gw], ke = g_rowptr[gw + 1];
    int k = kb;
    int i0, i1, i2, i3;
    if (k + 4 <= ke) {
        i0 = g_csr[k]; i1 = g_csr[k + 1]; i2 = g_csr[k + 2]; i3 = g_csr[k + 3];
    }
    while (k + 4 <= ke) {
        __half2 hv0[H2], hv1[H2], hv2[H2], hv3[H2];
        loadv(hv0, i0); loadv(hv1, i1); loadv(hv2, i2); loadv(hv3, i3);
        k += 4;
        if (k + 4 <= ke) {   // prefetch next group's indices
            i0 = g_csr[k]; i1 = g_csr[k + 1]; i2 = g_csr[k + 2]; i3 = g_csr[k + 3];
        }
        __half2 p[4];
        p[0] = score(hv0); p[1] = score(hv1); p[2] = score(hv2); p[3] = score(hv3);
#pragma unroll
        for (int off = 1; off < 8; off <<= 1) {
#pragma unroll
            for (int e = 0; e < 4; e++) {
                unsigned pu = __shfl_xor_sync(0xffffffffu,
                              *reinterpret_cast<unsigned*>(&p[e]), off);
                p[e] = __hadd2(p[e], *reinterpret_cast<__half2*>(&pu));
            }
        }
        float al[4];
#pragma unroll
        for (int e = 0; e < 4; e++) {
            float2 pf = __half22float2(p[e]);
            al[e] = exp2f(pf.x + pf.y);
        }
        s += (al[0] + al[1]) + (al[2] + al[3]);
#pragma unroll
        for (int i = 0; i < H2; i++) {
            float2 f0 = __half22float2(hv0[i]);
            float2 f1 = __half22float2(hv1[i]);
            float2 f2 = __half22float2(hv2[i]);
            float2 f3 = __half22float2(hv3[i]);
            acc[2*i]   += al[0]*f0.x + al[1]*f1.x + al[2]*f2.x + al[3]*f3.x;
            acc[2*i+1] += al[0]*f0.y + al[1]*f1.y + al[2]*f2.y + al[3]*f3.y;
        }
    }
    for (; k < ke; k++) {
        __half2 hv[H2];
        loadv(hv, g_csr[k]);
        __half2 p2 = score(hv);
#pragma unroll
        for (int off = 1; off < 8; off <<= 1) {
            unsigned pu = __shfl_xor_sync(0xffffffffu,
                          *reinterpret_cast<unsigned*>(&p2), off);
            p2 = __hadd2(p2, *reinterpret_cast<__half2*>(&pu));
        }
        float2 pf = __half22float2(p2);
        float al = exp2f(pf.x + pf.y);
        s += al;
#pragma unroll
        for (int i = 0; i < H2; i++) {
            float2 f = __half22float2(hv[i]);
            acc[2*i]   += al * f.x;
            acc[2*i+1] += al * f.y;
        }
    }

    float inv = 1.f / s;
#pragma unroll
    for (int i = 0; i < VPL; i++) acc[i] *= inv;
#pragma unroll
    for (int i = 0; i < VPL; i++) {
        acc[i] += __shfl_xor_sync(0xffffffffu, acc[i], 8);
        acc[i] += __shfl_xor_sync(0xffffffffu, acc[i], 16);
    }
    float u[VPL];
    const float* bp = bias + cl * VPL;
    float tot = 0.f;
#pragma unroll
    for (int i = 0; i < VPL; i++) { u[i] = acc[i] * 0.25f + bp[i]; tot += u[i]; }
#pragma unroll
    for (int off = 16; off >= 1; off >>= 1)
        tot += __shfl_xor_sync(0xffffffffu, tot, off);
    float mean = tot * (1.f / (4.f * C));
    float d[VPL], var = 0.f;
#pragma unroll
    for (int i = 0; i < VPL; i++) { d[i] = u[i] - mean; var += d[i] * d[i]; }
#pragma unroll
    for (int off = 16; off >= 1; off >>= 1)
        var += __shfl_xor_sync(0xffffffffu, var, off);
    float rstd = rsqrtf(var * (1.f / (4.f * C)) + 1e-5f);

    const float* gp = lng + cl * VPL;
    const float* b2 = lnb + cl * VPL;
    float y[VPL];
#pragma unroll
    for (int i = 0; i < VPL; i++)
        y[i] = fmaxf(d[i] * rstd * gp[i] + b2[i], 0.f);

    if (lane < 8) {
        if (FINAL) {
            int bg = batch[gw];
#pragma unroll
            for (int i = 0; i < VPL; i++)
                atomicAdd(&outp[bg * C + cl * VPL + i], y[i]);
        } else {
            float* op = outp + gw * C + cl * VPL;
            *reinterpret_cast<float4*>(op) = make_float4(y[0], y[1], y[2], y[3]);
            if (VPL == 8)
                *reinterpret_cast<float4*>(op + 4) = make_float4(y[4], y[5], y[6], y[7]);
        }
    }
}

// ---------------- kernel 5: layer-2 linear (half2 split-K) ----------------
__global__ void __launch_bounds__(512, 2)
lin2_kernel(const float* __restrict__ xin,
            const float* __restrict__ bl, const float* __restrict__ br,
            __half* __restrict__ xl, float* __restrict__ xr) {
    __shared__ __half2 xs2[32 * 32];
    int n0 = blockIdx.x * 32;
    int tid = threadIdx.x;
    for (int idx = tid; idx < 32 * 32; idx += 512) {
        int row = idx >> 5, kp = idx & 31;
        float2 v = *reinterpret_cast<const float2*>(xin + (n0 + row) * 64 + 2 * kp);
        xs2[idx] = __floats2half2_rn(v.x, v.y);
    }
    __syncthreads();

    int co = tid & 63;
    int r0 = (tid >> 6) * 4;
    int col = co * 4;
    bool left = (col < 128);
    const float* bptr = left ? (bl + col) : (br + col - 128);
    float4 bv = *reinterpret_cast<const float4*>(bptr);
    float4 accf[4];
#pragma unroll
    for (int i = 0; i < 4; i++) accf[i] = bv;

    const __half2* wp = g_w2h + co * 4;
#pragma unroll
    for (int ch = 0; ch < 2; ch++) {
        __half2 ah[4][4];
#pragma unroll
        for (int r = 0; r < 4; r++)
#pragma unroll
            for (int c = 0; c < 4; c++) ah[r][c] = __floats2half2_rn(0.f, 0.f);
#pragma unroll
        for (int kp = 0; kp < 16; kp++) {
            int kk = ch * 16 + kp;
            uint4 wv = *reinterpret_cast<const uint4*>(wp + kk * 256);
            __half2 w0 = *reinterpret_cast<__half2*>(&wv.x);
            __half2 w1 = *reinterpret_cast<__half2*>(&wv.y);
            __half2 w2 = *reinterpret_cast<__half2*>(&wv.z);
            __half2 w3 = *reinterpret_cast<__half2*>(&wv.w);
#pragma unroll
            for (int r = 0; r < 4; r++) {
                __half2 xp = xs2[(r0 + r) * 32 + kk];
                ah[r][0] = __hfma2(xp, w0, ah[r][0]);
                ah[r][1] = __hfma2(xp, w1, ah[r][1]);
                ah[r][2] = __hfma2(xp, w2, ah[r][2]);
                ah[r][3] = __hfma2(xp, w3, ah[r][3]);
            }
        }
#pragma unroll
        for (int r = 0; r < 4; r++) {
            float2 f;
            f = __half22float2(ah[r][0]); accf[r].x += f.x + f.y;
            f = __half22float2(ah[r][1]); accf[r].y += f.x + f.y;
            f = __half22float2(ah[r][2]); accf[r].z += f.x + f.y;
            f = __half22float2(ah[r][3]); accf[r].w += f.x + f.y;
        }
    }

    if (left) {
#pragma unroll
        for (int i = 0; i < 4; i++) {
            __half2* p = reinterpret_cast<__half2*>(xl + (n0 + r0 + i) * 128 + col);
            p[0] = __floats2half2_rn(accf[i].x, accf[i].y);
            p[1] = __floats2half2_rn(accf[i].z, accf[i].w);
        }
    } else {
        int oc = col - 128;
#pragma unroll
        for (int i = 0; i < 4; i++)
            *reinterpret_cast<float4*>(xr + (n0 + r0 + i) * 128 + oc) = accf[i];
    }
}

// ---------------- kernel 7: divide pooled sums ----------------
__global__ void div_kernel(const int* __restrict__ batch, float* __restrict__ out) {
    int t = threadIdx.x;
    if (t >= GG) return;
    int lo0 = 0, hi0 = NN;
    while (lo0 < hi0) { int mid = (lo0 + hi0) >> 1; if (batch[mid] < t) lo0 = mid + 1; else hi0 = mid; }
    int lo1 = lo0, hi1 = NN;
    while (lo1 < hi1) { int mid = (lo1 + hi1) >> 1; if (batch[mid] < t + 1) lo1 = mid + 1; else hi1 = mid; }
    float invc = 1.f / fmaxf((float)(lo1 - lo0), 1.f);
    float4* o4 = reinterpret_cast<float4*>(out + t * C2);
#pragma unroll
    for (int i = 0; i < C2 / 4; i++) {
        float4 v = o4[i];
        v.x *= invc; v.y *= invc; v.z *= invc; v.w *= invc;
        o4[i] = v;
    }
}

// ---------------- launch ----------------
extern "C" void kernel_launch(void* const* d_in, const int* in_sizes, int n_in,
                              void* d_out, int out_size) {
    const float* x     = (const float*)d_in[0];
    const int*   ei    = (const int*)  d_in[1];
    const int*   batch = (const int*)  d_in[2];
    const float* Wl1   = (const float*)d_in[3];
    const float* bl1   = (const float*)d_in[4];
    const float* Wr1   = (const float*)d_in[5];
    const float* br1   = (const float*)d_in[6];
    const float* att1  = (const float*)d_in[7];
    const float* b1    = (const float*)d_in[8];
    const float* ln1g  = (const float*)d_in[9];
    const float* ln1b  = (const float*)d_in[10];
    const float* Wl2   = (const float*)d_in[11];
    const float* bl2   = (const float*)d_in[12];
    const float* Wr2   = (const float*)d_in[13];
    const float* br2   = (const float*)d_in[14];
    const float* att2  = (const float*)d_in[15];
    const float* b2    = (const float*)d_in[16];
    const float* ln2g  = (const float*)d_in[17];
    const float* ln2b  = (const float*)d_in[18];
    float* out = (float*)d_out;

    __half* xl; float *xr, *h; int* degp;
    cudaGetSymbolAddress((void**)&xl,   g_xl);
    cudaGetSymbolAddress((void**)&xr,   g_xr);
    cudaGetSymbolAddress((void**)&h,    g_h);
    cudaGetSymbolAddress((void**)&degp, g_deg);

    cudaMemsetAsync(degp, 0, NN * sizeof(int));
    cudaMemsetAsync(out,  0, GG * C2 * sizeof(float));

    countprep_kernel<<<CNT_BLK + 32, 256>>>(ei, Wl2, Wr2);
    scan_kernel<<<1, 1024>>>();
    filllin1_kernel<<<FILL_BLK + NN / 8, 256>>>(ei, x, Wl1, bl1, Wr1, br1, xl, xr);
    gat_kernel<C1, false><<<NN / 4, 128>>>(xl, xr, att1, b1, ln1g, ln1b, batch, h);
    lin2_kernel<<<NN / 32, 512>>>(h, bl2, br2, xl, xr);
    gat_kernel<C2, true><<<NN / 4, 128>>>(xl, xr, att2, b2, ln2g, ln2b, batch, out);

    div_kernel<<<1, 256>>>(batch, out);
}